// round 1
// baseline (speedup 1.0000x reference)
#include <cuda_runtime.h>

#define B_    32
#define CIN   256
#define COUT  256
#define Hs    56
#define Ws    56
#define HW    (Hs*Ws)          // 3136
#define Mtot  (B_*HW)          // 100352
#define Kdim  (CIN*9)          // 2304
#define KZERO 128
#define NKT   (Kdim/16)        // 144

// device scratch (allocation-free rule: __device__ globals)
__device__ float d_s[B_*CIN];
__device__ float d_t[B_*COUT];

// ---------------------------------------------------------------------------
// Kernel 1: s[b,ci] = mean |x[b,ci,:,:]|
// ---------------------------------------------------------------------------
__global__ void absmean_kernel(const float* __restrict__ x) {
    int bc = blockIdx.x;  // b*CIN + ci
    const float4* p = (const float4*)(x + (size_t)bc * HW);
    float sum = 0.f;
    for (int j = threadIdx.x; j < HW/4; j += blockDim.x) {
        float4 v = p[j];
        sum += fabsf(v.x) + fabsf(v.y) + fabsf(v.z) + fabsf(v.w);
    }
    __shared__ float red[256];
    red[threadIdx.x] = sum;
    __syncthreads();
    for (int s = 128; s > 0; s >>= 1) {
        if (threadIdx.x < s) red[threadIdx.x] += red[threadIdx.x + s];
        __syncthreads();
    }
    if (threadIdx.x == 0) d_s[bc] = red[0] * (1.0f / HW);
}

// ---------------------------------------------------------------------------
// Kernel 2: gate. g = relu(s @ gate_w^T + gate_b); zero K smallest (stable
// tie-break by lower index, matching lax.top_k); renormalize *C_OUT.
// One block per batch row, 256 threads = 256 output channels.
// ---------------------------------------------------------------------------
__global__ void gate_kernel(const float* __restrict__ gw,
                            const float* __restrict__ gb) {
    int b = blockIdx.x;
    int c = threadIdx.x;
    __shared__ float s_sh[CIN];
    __shared__ float g_sh[COUT];
    __shared__ float red[256];

    s_sh[c] = d_s[b*CIN + c];
    __syncthreads();

    const float* wrow = gw + (size_t)c * CIN;
    float acc = gb[c];
    #pragma unroll 8
    for (int j = 0; j < CIN; j++) acc = fmaf(s_sh[j], wrow[j], acc);
    float g = fmaxf(acc, 0.f);
    g_sh[c] = g;
    __syncthreads();

    // rank = #{j : g[j] < g[c]} + #{j : g[j]==g[c], j<c}  (stable)
    int rank = 0;
    for (int j = 0; j < COUT; j++) {
        float gj = g_sh[j];
        rank += (gj < g) || (gj == g && j < c);
    }
    float t = (rank < KZERO) ? 0.f : g;

    red[c] = t;
    __syncthreads();
    for (int s = 128; s > 0; s >>= 1) {
        if (c < s) red[c] += red[c + s];
        __syncthreads();
    }
    d_t[b*COUT + c] = t * ((float)COUT / red[0]);
}

// ---------------------------------------------------------------------------
// Kernel 3: implicit-GEMM conv3x3 + BN + ReLU + gate scale (all fused).
// C[m,n], m=(b,h,w), n=c_out, k=ci*9+r*3+s. 128x128 tile, 8x8 per thread,
// K-chunk 16, double-buffered smem.
// ---------------------------------------------------------------------------
__global__ void __launch_bounds__(256)
conv_gemm_kernel(const float* __restrict__ x,  const float* __restrict__ cw,
                 const float* __restrict__ gamma, const float* __restrict__ beta,
                 const float* __restrict__ mean,  const float* __restrict__ var,
                 float* __restrict__ out)
{
    __shared__ float As[2][16][128];
    __shared__ float Bs[2][16][128];

    const int tid = threadIdx.x;
    const int mt  = blockIdx.y * 128;
    const int nt  = blockIdx.x * 128;

    // ---- loader indices (thread owns one m (and one n) column, 8 k's) ----
    const int ml = tid & 127;
    const int kg = tid >> 7;                 // 0 or 1
    const int m  = mt + ml;
    const int bb = m / HW;
    const int rem = m - bb * HW;
    const int hh = rem / Ws;
    const int ww = rem - hh * Ws;
    const float* xb   = x  + (size_t)bb * CIN * HW;
    const float* wrow = cw + (size_t)(nt + ml) * Kdim + kg;

    // ---- compute micro-tile indices ----
    const int rb = (tid & 15) * 8;
    const int cb = (tid >> 4) * 8;

    float acc[8][8];
    #pragma unroll
    for (int i = 0; i < 8; i++)
        #pragma unroll
        for (int j = 0; j < 8; j++) acc[i][j] = 0.f;

    float areg[8], breg[8];

    // prologue: chunk 0
    #pragma unroll
    for (int j = 0; j < 8; j++) {
        int k  = kg + 2*j;
        int ci = k / 9;
        int rs = k - ci*9;
        int dh = rs / 3;
        int dw = rs - dh*3;
        int hy = hh + dh - 1, wx = ww + dw - 1;
        areg[j] = ((unsigned)hy < Hs && (unsigned)wx < Ws)
                    ? xb[ci*HW + hy*Ws + wx] : 0.f;
        breg[j] = wrow[2*j];
    }
    #pragma unroll
    for (int j = 0; j < 8; j++) {
        As[0][kg + 2*j][ml] = areg[j];
        Bs[0][kg + 2*j][ml] = breg[j];
    }
    __syncthreads();

    for (int kt = 0; kt < NKT; kt++) {
        const int buf = kt & 1;

        if (kt + 1 < NKT) {
            const int k0 = (kt + 1) * 16 + kg;
            #pragma unroll
            for (int j = 0; j < 8; j++) {
                int k  = k0 + 2*j;
                int ci = k / 9;
                int rs = k - ci*9;
                int dh = rs / 3;
                int dw = rs - dh*3;
                int hy = hh + dh - 1, wx = ww + dw - 1;
                areg[j] = ((unsigned)hy < Hs && (unsigned)wx < Ws)
                            ? xb[ci*HW + hy*Ws + wx] : 0.f;
                breg[j] = wrow[(kt + 1) * 16 + 2*j];
            }
        }

        #pragma unroll
        for (int k = 0; k < 16; k++) {
            float a[8], bv[8];
            *(float4*)&a[0]  = *(const float4*)&As[buf][k][rb];
            *(float4*)&a[4]  = *(const float4*)&As[buf][k][rb + 4];
            *(float4*)&bv[0] = *(const float4*)&Bs[buf][k][cb];
            *(float4*)&bv[4] = *(const float4*)&Bs[buf][k][cb + 4];
            #pragma unroll
            for (int i = 0; i < 8; i++)
                #pragma unroll
                for (int j = 0; j < 8; j++)
                    acc[i][j] = fmaf(a[i], bv[j], acc[i][j]);
        }

        if (kt + 1 < NKT) {
            const int nb = buf ^ 1;
            #pragma unroll
            for (int j = 0; j < 8; j++) {
                As[nb][kg + 2*j][ml] = areg[j];
                Bs[nb][kg + 2*j][ml] = breg[j];
            }
        }
        __syncthreads();
    }

    // ---- epilogue: BN (folded) + ReLU + gate scale ----
    float inv_[8], add_[8];
    #pragma unroll
    for (int j = 0; j < 8; j++) {
        int n = nt + cb + j;
        float iv = gamma[n] / sqrtf(var[n] + 1e-5f);
        inv_[j] = iv;
        add_[j] = beta[n] - mean[n] * iv;
    }
    #pragma unroll
    for (int i = 0; i < 8; i++) {
        int mi = mt + rb + i;
        int bo = mi / HW;
        int ro = mi - bo * HW;
        float* op = out + (size_t)bo * COUT * HW + ro;
        const float* tp = d_t + bo * COUT;
        #pragma unroll
        for (int j = 0; j < 8; j++) {
            int n = nt + cb + j;
            float v = fmaf(acc[i][j], inv_[j], add_[j]);
            v = fmaxf(v, 0.f) * tp[n];
            op[(size_t)n * HW] = v;
        }
    }
}

// ---------------------------------------------------------------------------
extern "C" void kernel_launch(void* const* d_in, const int* in_sizes, int n_in,
                              void* d_out, int out_size) {
    const float* x     = (const float*)d_in[0];
    const float* cw    = (const float*)d_in[1];
    const float* gw    = (const float*)d_in[2];
    const float* gb    = (const float*)d_in[3];
    const float* gamma = (const float*)d_in[4];
    const float* beta  = (const float*)d_in[5];
    const float* mean  = (const float*)d_in[6];
    const float* var   = (const float*)d_in[7];
    float* out = (float*)d_out;

    absmean_kernel<<<B_*CIN, 256>>>(x);
    gate_kernel<<<B_, 256>>>(gw, gb);
    dim3 grid(COUT/128, Mtot/128);
    conv_gemm_kernel<<<grid, 256>>>(x, cw, gamma, beta, mean, var, out);
}

// round 3
// speedup vs baseline: 2.8023x; 2.8023x over previous
#include <cuda_runtime.h>
#include <cuda_bf16.h>
#include <cstdint>

#define B_    32
#define CIN   256
#define COUT  256
#define Hs    56
#define Ws    56
#define HW    3136
#define Mtot  100352
#define Kdim  2304
#define KZERO 128
#define NCH   108          /* K'' / 64 = 6912/64 */
#define CHPP  36           /* chunks per split-pass */

// ---------------- device scratch (static globals; no allocation) -----------
__device__ float d_s[B_*CIN];
__device__ float d_t[B_*COUT];
__device__ __nv_bfloat16 d_xhi[(size_t)B_*CIN*HW];
__device__ __nv_bfloat16 d_xlo[(size_t)B_*CIN*HW];
__device__ __align__(16) __nv_bfloat16 d_bimg[(size_t)NCH*256*64]; // pre-swizzled B tiles

// ---------------------------------------------------------------------------
// P0: split x into bf16 hi/lo + abs-mean
// ---------------------------------------------------------------------------
__global__ void prep_x_kernel(const float* __restrict__ x) {
    int bc = blockIdx.x;
    size_t base = (size_t)bc * HW;
    float sum = 0.f;
    for (int j = threadIdx.x; j < HW; j += 256) {
        float v = x[base + j];
        __nv_bfloat16 h = __float2bfloat16(v);
        d_xhi[base + j] = h;
        d_xlo[base + j] = __float2bfloat16(v - __bfloat162float(h));
        sum += fabsf(v);
    }
    __shared__ float red[256];
    red[threadIdx.x] = sum;
    __syncthreads();
    for (int s = 128; s > 0; s >>= 1) {
        if (threadIdx.x < s) red[threadIdx.x] += red[threadIdx.x + s];
        __syncthreads();
    }
    if (threadIdx.x == 0) d_s[bc] = red[0] * (1.0f / HW);
}

// ---------------------------------------------------------------------------
// P1: pre-swizzled B tile images. chunk c covers k'' in [64c, 64c+64);
// pass p = c/36: p0 -> w_hi, p1 -> w_lo, p2 -> w_hi. Tile layout = smem image:
// row n (0..255) of 128 bytes (64 bf16 along k), SW128-swizzled.
// ---------------------------------------------------------------------------
__global__ void prep_w_kernel(const float* __restrict__ cw) {
    int c = blockIdx.x;
    int n = threadIdx.x;
    int p = (c >= 2*CHPP) ? 2 : (c >= CHPP ? 1 : 0);
    int kbase = c*64 - p*Kdim;
    char* dst = (char*)(d_bimg + (size_t)c * 16384);
    const float* wr = cw + (size_t)n * Kdim + kbase;
    for (int kk = 0; kk < 64; kk++) {
        float v = wr[kk];
        __nv_bfloat16 h = __float2bfloat16(v);
        __nv_bfloat16 val = (p == 1) ? __float2bfloat16(v - __bfloat162float(h)) : h;
        uint32_t off = (uint32_t)(n*128 + kk*2);
        off ^= (off >> 3) & 0x70;
        *(__nv_bfloat16*)(dst + off) = val;
    }
}

// ---------------------------------------------------------------------------
// P2: gate (unchanged from passing R1)
// ---------------------------------------------------------------------------
__global__ void gate_kernel(const float* __restrict__ gw,
                            const float* __restrict__ gb) {
    int b = blockIdx.x;
    int c = threadIdx.x;
    __shared__ float s_sh[CIN];
    __shared__ float g_sh[COUT];
    __shared__ float red[256];

    s_sh[c] = d_s[b*CIN + c];
    __syncthreads();

    const float* wrow = gw + (size_t)c * CIN;
    float acc = gb[c];
    #pragma unroll 8
    for (int j = 0; j < CIN; j++) acc = fmaf(s_sh[j], wrow[j], acc);
    float g = fmaxf(acc, 0.f);
    g_sh[c] = g;
    __syncthreads();

    int rank = 0;
    for (int j = 0; j < COUT; j++) {
        float gj = g_sh[j];
        rank += (gj < g) || (gj == g && j < c);
    }
    float t = (rank < KZERO) ? 0.f : g;

    red[c] = t;
    __syncthreads();
    for (int s = 128; s > 0; s >>= 1) {
        if (c < s) red[c] += red[c + s];
        __syncthreads();
    }
    d_t[b*COUT + c] = t * ((float)COUT / red[0]);
}

// ---------------------------------------------------------------------------
// Main: mma.sync bf16 implicit GEMM (legacy tensor path; tcgen05 is not
// available on the harness's plain sm_103 PTX target).
// CTA: 128 m x 256 n, 16 warps, warp tile 32x64, K-chunk 64, double buffered.
// smem layout (dynamic):
//   [0,32768)       A tiles (2 bufs x 16KB)   row m: 128B (64 bf16), SW128
//   [32768,98304)   B tiles (2 bufs x 32KB)   row n: 128B (64 bf16), SW128
//   [98304,107520)  koff table (2304 u32)
//   [107520,108544) inv_s[256]
//   [108544,109568) add_s[256]
// ---------------------------------------------------------------------------
#define SM_A    0
#define SM_B    32768
#define SM_KOFF 98304
#define SM_INV  107520
#define SM_ADD  108544
#define SMEM_SZ 109568

__device__ __forceinline__ uint32_t smem_u32(const void* p) {
    uint32_t a;
    asm("{ .reg .u64 t; cvta.to.shared.u64 t, %1; cvt.u32.u64 %0, t; }" : "=r"(a) : "l"(p));
    return a;
}
__device__ __forceinline__ void ldmx4(uint32_t* r, uint32_t addr) {
    asm volatile("ldmatrix.sync.aligned.m8n8.x4.shared.b16 {%0,%1,%2,%3}, [%4];"
        : "=r"(r[0]), "=r"(r[1]), "=r"(r[2]), "=r"(r[3]) : "r"(addr));
}
__device__ __forceinline__ void mma16816(float* c, const uint32_t* a, const uint32_t* b) {
    asm volatile(
        "mma.sync.aligned.m16n8k16.row.col.f32.bf16.bf16.f32 "
        "{%0,%1,%2,%3}, {%4,%5,%6,%7}, {%8,%9}, {%0,%1,%2,%3};"
        : "+f"(c[0]), "+f"(c[1]), "+f"(c[2]), "+f"(c[3])
        : "r"(a[0]), "r"(a[1]), "r"(a[2]), "r"(a[3]), "r"(b[0]), "r"(b[1]));
}
__device__ __forceinline__ uint32_t sw128(uint32_t off) {
    return off ^ ((off >> 3) & 0x70);
}

__global__ void __launch_bounds__(512, 1)
conv_mma_kernel(const float* __restrict__ gamma, const float* __restrict__ beta,
                const float* __restrict__ mean,  const float* __restrict__ var,
                float* __restrict__ out)
{
    extern __shared__ __align__(1024) char smem[];
    uint32_t* koff_s = (uint32_t*)(smem + SM_KOFF);
    float* inv_s = (float*)(smem + SM_INV);
    float* add_s = (float*)(smem + SM_ADD);
    const uint32_t su = smem_u32(smem);

    const int t = threadIdx.x;
    const int lane = t & 31;
    const int wrp = t >> 5;            // 0..15
    const int wm = (wrp & 3) * 32;     // warp m offset in tile
    const int wn = (wrp >> 2) * 64;    // warp n offset

    // koff table: k -> (rs<<20) | (offset+64)
    for (int k = t; k < Kdim; k += 512) {
        int ci = k / 9, rs = k - ci*9;
        int dh = rs / 3, dw = rs - dh*3;
        int off = ci*HW + (dh-1)*Ws + (dw-1);
        koff_s[k] = ((uint32_t)rs << 20) | (uint32_t)(off + 64);
    }
    if (t < 256) {
        float iv = gamma[t] * rsqrtf(var[t] + 1e-5f);
        inv_s[t] = iv;
        add_s[t] = beta[t] - mean[t]*iv;
    }

    // ---- A loader geometry: thread owns one m-row, 4 k-groups of 4 ----
    const int mtile = blockIdx.x * 128;
    const int r = t & 127;
    const int kgb = t >> 7;            // 0..3
    {
    }
    const int m = mtile + r;
    const int bb = m / HW;
    const int rem = m - bb*HW;
    const int hh = rem / Ws;
    const int ww = rem - hh*Ws;
    const int boff = bb*(CIN*HW) + hh*Ws + ww;
    int msk = 0;
    #pragma unroll
    for (int rs = 0; rs < 9; rs++) {
        int dh = rs/3, dw = rs - dh*3;
        int hy = hh + dh - 1, wx = ww + dw - 1;
        if ((unsigned)hy < Hs && (unsigned)wx < Ws) msk |= (1 << rs);
    }
    uint32_t stA[4];
    #pragma unroll
    for (int q = 0; q < 4; q++)
        stA[q] = sw128((uint32_t)(r*128 + (kgb + 4*q)*8));

    // ---- ldmatrix lane address components (byte offsets before swizzle) ----
    // A frags (m16k16): lanes 0-15 rows, 16-31 rows with k+8
    const int a_row = (lane & 15);             // + wm + am*16
    const int a_kb  = (lane & 16) ? 16 : 0;
    // B frags x4 covering 2 n-blocks: rows n.. per mat layout
    const int b_row = ((lane & 16) ? 8 : 0) + (lane & 7);  // + wn + bp*16
    const int b_kb  = (lane & 8) ? 16 : 0;

    const unsigned short* xhi = (const unsigned short*)d_xhi;
    const unsigned short* xlo = (const unsigned short*)d_xlo;
    const uint4* bsrc = (const uint4*)d_bimg;

    float acc[2][8][4];
    #pragma unroll
    for (int i = 0; i < 2; i++)
        #pragma unroll
        for (int j = 0; j < 8; j++)
            #pragma unroll
            for (int q = 0; q < 4; q++) acc[i][j][q] = 0.f;

    // ---- prologue: load chunk 0 into buf 0 ----
    {
        const int c = 0;
        const unsigned short* sx = xhi;
        const int k0 = 0;
        char* abase = smem + SM_A;   // buf 0
        #pragma unroll
        for (int q = 0; q < 4; q++) {
            uint4 e = *(const uint4*)(koff_s + k0 + (kgb + 4*q)*4);
            uint32_t v0 = ((msk >> (e.x >> 20)) & 1) ? (uint32_t)sx[boff + (int)(e.x & 0xFFFFFu) - 64] : 0u;
            uint32_t v1 = ((msk >> (e.y >> 20)) & 1) ? (uint32_t)sx[boff + (int)(e.y & 0xFFFFFu) - 64] : 0u;
            uint32_t v2 = ((msk >> (e.z >> 20)) & 1) ? (uint32_t)sx[boff + (int)(e.z & 0xFFFFFu) - 64] : 0u;
            uint32_t v3 = ((msk >> (e.w >> 20)) & 1) ? (uint32_t)sx[boff + (int)(e.w & 0xFFFFFu) - 64] : 0u;
            *(uint2*)(abase + stA[q]) = make_uint2(v0 | (v1 << 16), v2 | (v3 << 16));
        }
        const uint4* src = bsrc + (size_t)c * 2048;
        uint4* dst = (uint4*)(smem + SM_B);
        #pragma unroll
        for (int q = 0; q < 4; q++) dst[q*512 + t] = src[q*512 + t];
    }
    __syncthreads();

    for (int c = 0; c < NCH; c++) {
        const int buf = c & 1;

        // ---- issue loads for chunk c+1 into registers ----
        uint2 sA[4];
        uint4 sB[4];
        const bool more = (c + 1 < NCH);
        if (more) {
            const int cn = c + 1;
            const int p = (cn >= 2*CHPP) ? 2 : (cn >= CHPP ? 1 : 0);
            const unsigned short* sx = (p == 2) ? xlo : xhi;
            const int k0 = cn*64 - p*Kdim;
            #pragma unroll
            for (int q = 0; q < 4; q++) {
                uint4 e = *(const uint4*)(koff_s + k0 + (kgb + 4*q)*4);
                uint32_t v0 = ((msk >> (e.x >> 20)) & 1) ? (uint32_t)sx[boff + (int)(e.x & 0xFFFFFu) - 64] : 0u;
                uint32_t v1 = ((msk >> (e.y >> 20)) & 1) ? (uint32_t)sx[boff + (int)(e.y & 0xFFFFFu) - 64] : 0u;
                uint32_t v2 = ((msk >> (e.z >> 20)) & 1) ? (uint32_t)sx[boff + (int)(e.z & 0xFFFFFu) - 64] : 0u;
                uint32_t v3 = ((msk >> (e.w >> 20)) & 1) ? (uint32_t)sx[boff + (int)(e.w & 0xFFFFFu) - 64] : 0u;
                sA[q] = make_uint2(v0 | (v1 << 16), v2 | (v3 << 16));
            }
            const uint4* src = bsrc + (size_t)(c+1) * 2048;
            #pragma unroll
            for (int q = 0; q < 4; q++) sB[q] = src[q*512 + t];
        }

        // ---- compute 4 k16 steps from smem[buf] ----
        const uint32_t Ab = su + SM_A + buf*16384;
        const uint32_t Bb = su + SM_B + buf*32768;
        #pragma unroll
        for (int ks = 0; ks < 4; ks++) {
            uint32_t af[2][4];
            #pragma unroll
            for (int am = 0; am < 2; am++) {
                uint32_t off = (uint32_t)((wm + am*16 + a_row)*128 + ks*32 + a_kb);
                ldmx4(af[am], Ab + sw128(off));
            }
            uint32_t bf[8][2];
            #pragma unroll
            for (int bp = 0; bp < 4; bp++) {
                uint32_t rr[4];
                uint32_t off = (uint32_t)((wn + bp*16 + b_row)*128 + ks*32 + b_kb);
                ldmx4(rr, Bb + sw128(off));
                bf[2*bp][0] = rr[0]; bf[2*bp][1] = rr[1];
                bf[2*bp+1][0] = rr[2]; bf[2*bp+1][1] = rr[3];
            }
            #pragma unroll
            for (int am = 0; am < 2; am++)
                #pragma unroll
                for (int bn = 0; bn < 8; bn++)
                    mma16816(acc[am][bn], af[am], bf[bn]);
        }

        // ---- store staged chunk c+1 into smem[buf^1] ----
        if (more) {
            char* abase = smem + SM_A + (buf^1)*16384;
            #pragma unroll
            for (int q = 0; q < 4; q++)
                *(uint2*)(abase + stA[q]) = sA[q];
            uint4* dst = (uint4*)(smem + SM_B + (buf^1)*32768);
            #pragma unroll
            for (int q = 0; q < 4; q++) dst[q*512 + t] = sB[q];
        }
        __syncthreads();
    }

    // ---- epilogue: BN + ReLU + gate, write NCHW ----
    #pragma unroll
    for (int am = 0; am < 2; am++) {
        int mr0 = mtile + wm + am*16 + (lane >> 2);
        #pragma unroll
        for (int half = 0; half < 2; half++) {
            int mr = mr0 + half*8;
            int b = mr / HW;
            int rm = mr - b*HW;
            float* op = out + (size_t)b*(COUT*HW) + rm;
            const float* tp = d_t + b*COUT;
            #pragma unroll
            for (int bn = 0; bn < 8; bn++) {
                int n = wn + bn*8 + 2*(lane & 3);
                float v0 = fmaf(acc[am][bn][half*2+0], inv_s[n],   add_s[n]);
                float v1 = fmaf(acc[am][bn][half*2+1], inv_s[n+1], add_s[n+1]);
                v0 = fmaxf(v0, 0.f) * __ldg(tp + n);
                v1 = fmaxf(v1, 0.f) * __ldg(tp + n + 1);
                op[(size_t)n * HW] = v0;
                op[(size_t)(n+1) * HW] = v1;
            }
        }
    }
}

// ---------------------------------------------------------------------------
extern "C" void kernel_launch(void* const* d_in, const int* in_sizes, int n_in,
                              void* d_out, int out_size) {
    const float* x     = (const float*)d_in[0];
    const float* cw    = (const float*)d_in[1];
    const float* gw    = (const float*)d_in[2];
    const float* gb    = (const float*)d_in[3];
    const float* gamma = (const float*)d_in[4];
    const float* beta  = (const float*)d_in[5];
    const float* mean  = (const float*)d_in[6];
    const float* var   = (const float*)d_in[7];
    float* out = (float*)d_out;

    static bool attr_set = false;
    if (!attr_set) {
        cudaFuncSetAttribute(conv_mma_kernel,
                             cudaFuncAttributeMaxDynamicSharedMemorySize, SMEM_SZ);
        attr_set = true;
    }

    prep_x_kernel<<<B_*CIN, 256>>>(x);
    gate_kernel<<<B_, 256>>>(gw, gb);
    prep_w_kernel<<<NCH, 256>>>(cw);
    conv_mma_kernel<<<Mtot/128, 512, SMEM_SZ>>>(gamma, beta, mean, var, out);
}